// round 14
// baseline (speedup 1.0000x reference)
#include <cuda_runtime.h>
#include <cuda_bf16.h>
#include <cuda_fp16.h>
#include <cstdint>

// Problem constants
#define BB 2
#define CC 256
#define NN 4096          // 64*64
#define DD 768           // 3*CC
#define IN 32            // inter

// Flash tiling
#define TMQ 128          // q rows per block
#define TNK 256          // keys per j-tile
#define KC 128           // feature chunk (two stacked 128B SW128 sub-tiles)
#define NCH (DD / KC)    // 6
#define SPLITS 2
#define NSPL (SPLITS * 2)    // splits x col-halves
#define KEYS (NN / SPLITS)   // 2048
#define NJT (KEYS / TNK)     // 8

// SMEM layout (bytes) for flash
#define QSUB   16384           // Q sub-tile (128 rows x 128B)
#define KSUB   32768           // K sub-tile (256 rows x 128B)
#define KOFF   32768           // Q total = 2 subs = 32KB
#define STAGE_BYTES 98304      // Q 32K + K 64K
#define VTS_OFF 196608         // 2 x fp16 VT [32][272] (pitch 544B)
#define VT_PITCH 544
#define VT_STAGE 17408
#define FLASH_SMEM 231424

#define SQRT_LOG2E 1.2011224087864498f

// Scratch (static device globals; no allocation)
__device__ float d_M[BB][2 * CC][NN];                     // pooled variants 3,5 (fp32)
__device__ __align__(16) __nv_bfloat16 d_Mt[BB][NN][DD];  // token-major, scaled (incl sqrt(log2e)), bf16
__device__ __align__(16) __half d_GXT[BB][IN][NN];        // g_x as [b][i][n], fp16
__device__ float d_S[3][BB][CC];
__device__ float d_sqrtV[BB][3];
__device__ float d_part[BB * NSPL][NN][IN];               // partial O (unnormalized)
__device__ float2 d_ml[BB * NSPL][NN];                    // partial (m, l), m in log2 domain

// ---------------- helpers ----------------
__device__ __forceinline__ uint32_t smem_u32(const void* p) {
    uint32_t a;
    asm("{ .reg .u64 t; cvta.to.shared.u64 t, %1; cvt.u32.u64 %0, t; }" : "=r"(a) : "l"(p));
    return a;
}
__device__ __forceinline__ uint32_t sw128(uint32_t bo) { return bo ^ ((bo >> 3) & 0x70); }

__device__ __forceinline__ void cpa16(uint32_t dst, const void* src) {
    asm volatile("cp.async.cg.shared.global [%0], [%1], 16;" :: "r"(dst), "l"(src));
}
__device__ __forceinline__ void cp_commit() { asm volatile("cp.async.commit_group;"); }
__device__ __forceinline__ void cp_wait0() { asm volatile("cp.async.wait_group 0;"); }
__device__ __forceinline__ void cp_wait1() { asm volatile("cp.async.wait_group 1;"); }

__device__ __forceinline__ void ldsm4(uint32_t* r, uint32_t addr) {
    asm volatile("ldmatrix.sync.aligned.m8n8.x4.shared.b16 {%0,%1,%2,%3}, [%4];"
                 : "=r"(r[0]), "=r"(r[1]), "=r"(r[2]), "=r"(r[3]) : "r"(addr));
}
__device__ __forceinline__ void mma_bf16(float* c, const uint32_t* a, uint32_t b0, uint32_t b1) {
    asm volatile("mma.sync.aligned.m16n8k16.row.col.f32.bf16.bf16.f32 "
                 "{%0,%1,%2,%3},{%4,%5,%6,%7},{%8,%9},{%0,%1,%2,%3};"
                 : "+f"(c[0]), "+f"(c[1]), "+f"(c[2]), "+f"(c[3])
                 : "r"(a[0]), "r"(a[1]), "r"(a[2]), "r"(a[3]), "r"(b0), "r"(b1));
}
__device__ __forceinline__ void mma_f16(float* c, const uint32_t* a, uint32_t b0, uint32_t b1) {
    asm volatile("mma.sync.aligned.m16n8k16.row.col.f32.f16.f16.f32 "
                 "{%0,%1,%2,%3},{%4,%5,%6,%7},{%8,%9},{%0,%1,%2,%3};"
                 : "+f"(c[0]), "+f"(c[1]), "+f"(c[2]), "+f"(c[3])
                 : "r"(a[0]), "r"(a[1]), "r"(a[2]), "r"(a[3]), "r"(b0), "r"(b1));
}
__device__ __forceinline__ float qredmax(float v) {
    v = fmaxf(v, __shfl_xor_sync(0xffffffffu, v, 1));
    v = fmaxf(v, __shfl_xor_sync(0xffffffffu, v, 2));
    return v;
}
__device__ __forceinline__ float qredsum(float v) {
    v += __shfl_xor_sync(0xffffffffu, v, 1);
    v += __shfl_xor_sync(0xffffffffu, v, 2);
    return v;
}

// ---------------- kernel 1: MERGED pool + gx (R10-proven) ----------------
__global__ __launch_bounds__(256) void prep_kernel(const float* __restrict__ x,
                                                   const float* __restrict__ Wg) {
    __shared__ __align__(16) char smraw[49152];
    const int bid = blockIdx.x;
    const int t = threadIdx.x;

    if (bid < 512) {
        const int c = bid & 255, b = bid >> 8;
        const float* xp = x + ((size_t)(b * CC + c)) * NN;
        float (*xs)[64] = (float (*)[64])smraw;
        float (*h3)[64] = (float (*)[64])(smraw + 16384);
        float (*h5)[64] = (float (*)[64])(smraw + 32768);

        for (int p = t; p < NN; p += 256) xs[p >> 6][p & 63] = xp[p];
        __syncthreads();
        for (int p = t; p < NN; p += 256) {
            int h = p >> 6, w = p & 63;
            float c0 = xs[h][w];
            float l1 = (w > 0)  ? xs[h][w - 1] : 0.f;
            float r1 = (w < 63) ? xs[h][w + 1] : 0.f;
            float l2 = (w > 1)  ? xs[h][w - 2] : 0.f;
            float r2 = (w < 62) ? xs[h][w + 2] : 0.f;
            h3[h][w] = l1 + c0 + r1;
            h5[h][w] = l2 + l1 + c0 + r1 + r2;
        }
        __syncthreads();
        float s1 = 0.f, s3 = 0.f, s5 = 0.f;
        float* M3 = &d_M[b][c][0];
        float* M5 = &d_M[b][CC + c][0];
        for (int p = t; p < NN; p += 256) {
            int h = p >> 6, w = p & 63;
            float v0 = xs[h][w];
            float u1 = (h > 0)  ? h3[h - 1][w] : 0.f;
            float dn1 = (h < 63) ? h3[h + 1][w] : 0.f;
            float u2 = (h > 1)  ? h5[h - 2][w] : 0.f;
            float dn2 = (h < 62) ? h5[h + 2][w] : 0.f;
            float u1b = (h > 0)  ? h5[h - 1][w] : 0.f;
            float dn1b = (h < 63) ? h5[h + 1][w] : 0.f;
            float p3 = (u1 + h3[h][w] + dn1) * (1.f / 9.f);
            float p5 = (u2 + u1b + h5[h][w] + dn1b + dn2) * (1.f / 25.f);
            M3[p] = p3; M5[p] = p5;
            s1 += v0; s3 += p3; s5 += p5;
        }
        __syncthreads();
        float* r1 = (float*)smraw;
        float* r3 = (float*)(smraw + 16384);
        float* r5 = (float*)(smraw + 32768);
        r1[t] = s1; r3[t] = s3; r5[t] = s5;
        __syncthreads();
        for (int off = 128; off > 0; off >>= 1) {
            if (t < off) { r1[t] += r1[t + off]; r3[t] += r3[t + off]; r5[t] += r5[t + off]; }
            __syncthreads();
        }
        if (t == 0) {
            d_S[0][b][c] = r1[0];
            d_S[1][b][c] = r3[0];
            d_S[2][b][c] = r5[0];
        }
    } else {
        const int gid = bid - 512;
        const int b = gid >> 7;
        const int n0 = (gid & 127) * 32;
        float (*Wgs)[33] = (float (*)[33])smraw;
        float* xsb = (float*)(smraw + 33792);
        const uint32_t xsb_u = smem_u32(xsb);
        const int i = t & 31, ng = t >> 5;
        const float* xb = x + (size_t)b * CC * NN;

        {
            int r = t >> 3, q = t & 7;
            cpa16(xsb_u + (r * 32 + q * 4) * 4, &xb[(size_t)r * NN + n0 + q * 4]);
            cp_commit();
        }
        #pragma unroll
        for (int it = 0; it < 32; it++) {
            int e = it * 256 + t;
            int ii = e >> 8, cc = e & 255;
            Wgs[cc][ii] = Wg[ii * CC + cc];
        }

        float acc[4] = {0.f, 0.f, 0.f, 0.f};
        for (int c = 0; c < 8; c++) {
            if (c + 1 < 8) {
                int r = t >> 3, q = t & 7;
                cpa16(xsb_u + (((c + 1) % 3) * 1024 + r * 32 + q * 4) * 4,
                      &xb[(size_t)((c + 1) * 32 + r) * NN + n0 + q * 4]);
                cp_commit();
                cp_wait1();
            } else {
                cp_wait0();
            }
            __syncthreads();
            const float* xsc = &xsb[(c % 3) * 1024];
            const int cbase = c * 32;
            #pragma unroll
            for (int cc = 0; cc < 32; cc++) {
                float w = Wgs[cbase + cc][i];
                float4 xv = *(const float4*)&xsc[cc * 32 + ng * 4];
                acc[0] += w * xv.x; acc[1] += w * xv.y; acc[2] += w * xv.z; acc[3] += w * xv.w;
            }
        }
        __half hv[4];
        #pragma unroll
        for (int j = 0; j < 4; j++) hv[j] = __float2half(acc[j]);
        *(uint2*)&d_GXT[b][i][n0 + ng * 4] = *(uint2*)hv;
    }
}

// ---------------- kernel 2: tiny V computation ----------------
__global__ void vcalc_kernel(const float* __restrict__ W1, const float* __restrict__ W2) {
    __shared__ float m[BB][3];
    const int t = threadIdx.x;
    if (t < 6) {
        int k = t % 3, b = t / 3;
        float s = 0.f;
        for (int c = 0; c < CC; c++) { float v = d_S[k][b][c]; s += v * v; }
        m[b][k] = s * (1.f / ((float)NN * (float)NN));
    }
    __syncthreads();
    if (t < BB) {
        int b = t;
        float h[16];
        #pragma unroll
        for (int i = 0; i < 16; i++)
            h[i] = W1[i * 3 + 0] * m[b][0] + W1[i * 3 + 1] * m[b][1] + W1[i * 3 + 2] * m[b][2];
        float o[3];
        #pragma unroll
        for (int j = 0; j < 3; j++) {
            float s = 0.f;
            #pragma unroll
            for (int i = 0; i < 16; i++) s += W2[j * 16 + i] * h[i];
            o[j] = s;
        }
        float mx = fmaxf(o[0], fmaxf(o[1], o[2]));
        float e0 = expf(o[0] - mx), e1 = expf(o[1] - mx), e2 = expf(o[2] - mx);
        float inv = 1.f / (e0 + e1 + e2);
        d_sqrtV[b][0] = sqrtf(e0 * inv);
        d_sqrtV[b][1] = sqrtf(e1 * inv);
        d_sqrtV[b][2] = sqrtf(e2 * inv);
    }
}

// ---------------- kernel 2b: transpose + scale (incl sqrt(log2e)) + bf16 ----------------
__global__ void split_kernel(const float* __restrict__ x) {
    const int b = blockIdx.y;
    const int dtile = blockIdx.x % 12;
    const int ntile = blockIdx.x / 12;
    const int d0 = dtile * 64, n0 = ntile * 64;
    const float s = d_sqrtV[b][dtile >> 2] * SQRT_LOG2E;
    const float* src = (dtile < 4) ? (x + ((size_t)b * CC + d0) * NN)
                                   : &d_M[b][d0 - CC][0];
    __shared__ float sme[64][65];
    const int t = threadIdx.x;
    #pragma unroll
    for (int it = 0; it < 4; it++) {
        int e = it * 256 + t;
        int r = e >> 4, c4 = (e & 15) << 2;
        float4 v = *(const float4*)&src[(size_t)r * NN + n0 + c4];
        sme[r][c4] = v.x; sme[r][c4 + 1] = v.y; sme[r][c4 + 2] = v.z; sme[r][c4 + 3] = v.w;
    }
    __syncthreads();
    #pragma unroll
    for (int it = 0; it < 2; it++) {
        int e = it * 256 + t;
        int r2 = e >> 3, g = e & 7;
        __nv_bfloat16 hv[8];
        #pragma unroll
        for (int q = 0; q < 8; q++)
            hv[q] = __float2bfloat16(sme[g * 8 + q][r2] * s);
        *(uint4*)&d_Mt[b][n0 + r2][d0 + g * 8] = *(uint4*)hv;
    }
}

// ---------------- kernel 4: split-K flash, KC=128, exp2 domain ----------------
// grid (32, SPLITS, BB), 256 threads (8 warps).
// warp: wr=warp>>1 rows wr*32..+31; wc=warp&1 cols wc*128..+127 (own (m,l,O) partial).
__global__ __launch_bounds__(256, 1) void flash10_kernel() {
    extern __shared__ __align__(16) char sm[];
    const uint32_t sb = smem_u32(sm);
    const int tid = threadIdx.x, warp = tid >> 5, lane = tid & 31;
    const int i0 = blockIdx.x * TMQ;
    const int split = blockIdx.y;
    const int b = blockIdx.z;
    const int wr = warp >> 1, wc = warp & 1;

    const int nl = (lane & 7) | ((lane & 16) >> 1);
    const int kh = (lane >> 3) & 1;

    float m_[2][2], l_[2][2];
    #pragma unroll
    for (int rt = 0; rt < 2; rt++) { m_[rt][0] = -3.0e38f; m_[rt][1] = -3.0e38f; l_[rt][0] = 0.f; l_[rt][1] = 0.f; }

    float yacc[2][4][4];
    #pragma unroll
    for (int rt = 0; rt < 2; rt++)
        #pragma unroll
        for (int ng = 0; ng < 4; ng++)
            #pragma unroll
            for (int q = 0; q < 4; q++) yacc[rt][ng][q] = 0.f;

    const __nv_bfloat16* Mb = &d_Mt[b][0][0];

    // load one Q+K chunk (d0 = feature base) into stage buffer qb
    auto load_chunk = [&](uint32_t qb, int j0, int d0) {
        #pragma unroll
        for (int it = 0; it < 8; it++) {
            int e = it * 256 + tid;
            int r = e >> 4, g = e & 15;
            int sub = g >> 3, go = g & 7;
            cpa16(qb + sub * QSUB + sw128(r * 128 + go * 16),
                  Mb + (size_t)(i0 + r) * DD + d0 + sub * 64 + go * 8);
        }
        #pragma unroll
        for (int it = 0; it < 16; it++) {
            int e = it * 256 + tid;
            int r = e >> 4, g = e & 15;
            int sub = g >> 3, go = g & 7;
            cpa16(qb + KOFF + sub * KSUB + sw128(r * 128 + go * 16),
                  Mb + (size_t)(j0 + r) * DD + d0 + sub * 64 + go * 8);
        }
    };

    // prologue for tile jt: chunk 0 into stage 0 + VT into buffer jt&1
    auto prologue = [&](int jt) {
        const int j0 = split * KEYS + jt * TNK;
        load_chunk(sb, j0, 0);
        const uint32_t vb = sb + VTS_OFF + (jt & 1) * VT_STAGE;
        #pragma unroll
        for (int it = 0; it < 4; it++) {
            int e = it * 256 + tid, r = e >> 5, g = e & 31;
            cpa16(vb + r * VT_PITCH + g * 16, &d_GXT[b][r][j0 + g * 8]);
        }
        cp_commit();
    };
    prologue(0);

    for (int jt = 0; jt < NJT; jt++) {
        const int j0 = split * KEYS + jt * TNK;

        float acc[2][16][4];
        #pragma unroll
        for (int rt = 0; rt < 2; rt++)
            #pragma unroll
            for (int t = 0; t < 16; t++)
                #pragma unroll
                for (int q = 0; q < 4; q++) acc[rt][t][q] = 0.f;

        for (int c = 0; c < NCH; c++) {
            cp_wait0();
            __syncthreads();
            if (c + 1 < NCH) {
                load_chunk(sb + ((c + 1) & 1) * STAGE_BYTES, j0, (c + 1) * KC);
                cp_commit();
            }
            const uint32_t qb = sb + (c & 1) * STAGE_BYTES;
            const uint32_t kb = qb + KOFF;
            #pragma unroll
            for (int k16 = 0; k16 < 8; k16++) {
                const int sub = k16 >> 2, kk = k16 & 3;
                uint32_t afr[2][4];
                ldsm4(afr[0], qb + sub * QSUB + sw128((wr * 32 + (lane & 15)) * 128 + kk * 32 + (lane >> 4) * 16));
                ldsm4(afr[1], qb + sub * QSUB + sw128((wr * 32 + 16 + (lane & 15)) * 128 + kk * 32 + (lane >> 4) * 16));
                #pragma unroll
                for (int nt = 0; nt < 8; nt++) {
                    uint32_t bfr[4];
                    ldsm4(bfr, kb + sub * KSUB + sw128((wc * 128 + nt * 16 + nl) * 128 + kk * 32 + kh * 16));
                    mma_bf16(acc[0][2 * nt],     afr[0], bfr[0], bfr[1]);
                    mma_bf16(acc[0][2 * nt + 1], afr[0], bfr[2], bfr[3]);
                    mma_bf16(acc[1][2 * nt],     afr[1], bfr[0], bfr[1]);
                    mma_bf16(acc[1][2 * nt + 1], afr[1], bfr[2], bfr[3]);
                }
            }
        }

        // hoist next tile's chunk-0 + VT loads over the serial phase
        if (jt + 1 < NJT) prologue(jt + 1);

        // ---- warp-local online softmax (barrier-free, log2 domain) ----
        float mna[2], mnb[2];
        #pragma unroll
        for (int rt = 0; rt < 2; rt++) {
            float ma = -3.0e38f, mb2 = -3.0e38f;
            #pragma unroll
            for (int t = 0; t < 16; t++) {
                ma  = fmaxf(ma,  fmaxf(acc[rt][t][0], acc[rt][t][1]));
                mb2 = fmaxf(mb2, fmaxf(acc[rt][t][2], acc[rt][t][3]));
            }
            ma = qredmax(ma); mb2 = qredmax(mb2);
            float na = fmaxf(m_[rt][0], ma), nb = fmaxf(m_[rt][1], mb2);
            float sca = exp2f(m_[rt][0] - na), scb = exp2f(m_[rt][1] - nb);
            m_[rt][0] = na; m_[rt][1] = nb;
            l_[rt][0] *= sca; l_[rt][1] *= scb;
            mna[rt] = na; mnb[rt] = nb;
            #pragma unroll
            for (int ng = 0; ng < 4; ng++) {
                yacc[rt][ng][0] *= sca; yacc[rt][ng][1] *= sca;
                yacc[rt][ng][2] *= scb; yacc[rt][ng][3] *= scb;
            }
        }

        // ---- fused exp2 + PV (P in registers; VT double-buffered) ----
        const uint32_t vtb = sb + VTS_OFF + (jt & 1) * VT_STAGE;
        float sa[2] = {0.f, 0.f}, sb2[2] = {0.f, 0.f};
        #pragma unroll
        for (int t = 0; t < 8; t++) {
            uint32_t bfr0[4], bfr1[4];
            ldsm4(bfr0, vtb + nl * VT_PITCH        + wc * 256 + t * 32 + kh * 16);
            ldsm4(bfr1, vtb + (16 + nl) * VT_PITCH + wc * 256 + t * 32 + kh * 16);
            #pragma unroll
            for (int rt = 0; rt < 2; rt++) {
                float e0 = exp2f(acc[rt][2 * t][0] - mna[rt]);
                float e1 = exp2f(acc[rt][2 * t][1] - mna[rt]);
                float e2 = exp2f(acc[rt][2 * t][2] - mnb[rt]);
                float e3 = exp2f(acc[rt][2 * t][3] - mnb[rt]);
                float e4 = exp2f(acc[rt][2 * t + 1][0] - mna[rt]);
                float e5 = exp2f(acc[rt][2 * t + 1][1] - mna[rt]);
                float e6 = exp2f(acc[rt][2 * t + 1][2] - mnb[rt]);
                float e7 = exp2f(acc[rt][2 * t + 1][3] - mnb[rt]);
                sa[rt]  += e0 + e1 + e4 + e5;
                sb2[rt] += e2 + e3 + e6 + e7;
                uint32_t a[4];
                __half2 h;
                h = __floats2half2_rn(e0, e1); a[0] = *(uint32_t*)&h;
                h = __floats2half2_rn(e2, e3); a[1] = *(uint32_t*)&h;
                h = __floats2half2_rn(e4, e5); a[2] = *(uint32_t*)&h;
                h = __floats2half2_rn(e6, e7); a[3] = *(uint32_t*)&h;
                mma_f16(yacc[rt][0], a, bfr0[0], bfr0[1]);
                mma_f16(yacc[rt][1], a, bfr0[2], bfr0[3]);
                mma_f16(yacc[rt][2], a, bfr1[0], bfr1[1]);
                mma_f16(yacc[rt][3], a, bfr1[2], bfr1[3]);
            }
        }
        #pragma unroll
        for (int rt = 0; rt < 2; rt++) {
            l_[rt][0] += qredsum(sa[rt]);
            l_[rt][1] += qredsum(sb2[rt]);
        }
    }

    // ---- epilogue: straight register->global partial store (no barriers) ----
    const int sidx = (b * SPLITS + split) * 2 + wc;
    #pragma unroll
    for (int rt = 0; rt < 2; rt++) {
        int rowa = i0 + wr * 32 + rt * 16 + (lane >> 2);
        #pragma unroll
        for (int ng = 0; ng < 4; ng++) {
            int col = ng * 8 + (lane & 3) * 2;
            *(float2*)&d_part[sidx][rowa][col]     = make_float2(yacc[rt][ng][0], yacc[rt][ng][1]);
            *(float2*)&d_part[sidx][rowa + 8][col] = make_float2(yacc[rt][ng][2], yacc[rt][ng][3]);
        }
        if ((lane & 3) == 0) {
            d_ml[sidx][rowa]     = make_float2(m_[rt][0], l_[rt][0]);
            d_ml[sidx][rowa + 8] = make_float2(m_[rt][1], l_[rt][1]);
        }
    }
}

// ---------------- kernel 5: 4-way partial combine + Ww conv + residual ----------------
__global__ void combine_kernel(const float* __restrict__ x,
                               const float* __restrict__ Ww,
                               float* __restrict__ out) {
    const int b = blockIdx.y;
    const int r0 = blockIdx.x * 64;
    __shared__ float ysT[32][68];
    __shared__ float Ws[CC * IN];
    __shared__ float wS[NSPL][64];
    const int t = threadIdx.x;
    if (t < 64) {
        float2 ml[NSPL];
        float m = -3.0e38f;
        #pragma unroll
        for (int s = 0; s < NSPL; s++) {
            ml[s] = d_ml[b * NSPL + s][r0 + t];
            m = fmaxf(m, ml[s].x);
        }
        float lsum = 0.f, w[NSPL];
        #pragma unroll
        for (int s = 0; s < NSPL; s++) {
            w[s] = exp2f(ml[s].x - m);   // m's are in log2 domain
            lsum += ml[s].y * w[s];
        }
        float inv = 1.f / lsum;
        #pragma unroll
        for (int s = 0; s < NSPL; s++) wS[s][t] = w[s] * inv;
    }
    #pragma unroll
    for (int it = 0; it < 32; it++) Ws[it * 256 + t] = Ww[it * 256 + t];
    __syncthreads();
    for (int idx = t; idx < 64 * IN; idx += 256) {
        int rl = idx >> 5, col = idx & 31;
        float acc = 0.f;
        #pragma unroll
        for (int s = 0; s < NSPL; s++)
            acc += d_part[b * NSPL + s][r0 + rl][col] * wS[s][rl];
        ysT[col][rl] = acc;
    }
    __syncthreads();

    const int r = t & 63;
    const int cg = t >> 6;
    float yreg[IN];
    #pragma unroll
    for (int i = 0; i < IN; i++) yreg[i] = ysT[i][r];
    const float* xb = x + (size_t)b * CC * NN;
    float* ob = out + (size_t)b * CC * NN;
    #pragma unroll 4
    for (int k = 0; k < 64; k++) {
        int c = cg * 64 + k;
        float s = 0.f;
        #pragma unroll
        for (int q = 0; q < 8; q++) {
            float4 w4 = *(const float4*)&Ws[c * 32 + q * 4];
            s += w4.x * yreg[q * 4] + w4.y * yreg[q * 4 + 1] + w4.z * yreg[q * 4 + 2] + w4.w * yreg[q * 4 + 3];
        }
        ob[(size_t)c * NN + r0 + r] = s + xb[(size_t)c * NN + r0 + r];
    }
}

extern "C" void kernel_launch(void* const* d_in, const int* in_sizes, int n_in,
                              void* d_out, int out_size) {
    const float* x  = (const float*)d_in[0];
    const float* Wg = (const float*)d_in[1];
    const float* Ww = (const float*)d_in[2];
    const float* W1 = (const float*)d_in[3];
    const float* W2 = (const float*)d_in[4];
    float* out = (float*)d_out;

    static int configured = 0;
    if (!configured) {
        cudaFuncSetAttribute(flash10_kernel, cudaFuncAttributeMaxDynamicSharedMemorySize, FLASH_SMEM);
        configured = 1;
    }

    prep_kernel<<<768, 256>>>(x, Wg);
    vcalc_kernel<<<1, 64>>>(W1, W2);
    split_kernel<<<dim3(12 * (NN / 64), BB), 256>>>(x);
    flash10_kernel<<<dim3(NN / TMQ, SPLITS, BB), 256, FLASH_SMEM>>>();
    combine_kernel<<<dim3(NN / 64, BB), 256>>>(x, Ww, out);
}

// round 15
// speedup vs baseline: 1.0053x; 1.0053x over previous
#include <cuda_runtime.h>
#include <cuda_bf16.h>
#include <cuda_fp16.h>
#include <cstdint>

// Problem constants
#define BB 2
#define CC 256
#define NN 4096          // 64*64
#define DD 768           // 3*CC
#define IN 32            // inter

// Flash tiling (R13-proven geometry)
#define TMQ 128          // q rows per block
#define TNK 256          // keys per j-tile
#define KC 64            // feature chunk (=128B bf16 row)
#define NCH (DD / KC)    // 12
#define SPLITS 2
#define NSPL (SPLITS * 2)    // splits x col-halves
#define KEYS (NN / SPLITS)   // 2048
#define NJT (KEYS / TNK)     // 8

// SMEM layout (bytes) for flash
#define KOFF   16384
#define STAGE_BYTES 49152      // Q 16K + K 32K
#define VTS_OFF 98304          // 2 x fp16 VT [32][272] (pitch 544B)
#define VT_PITCH 544
#define VT_STAGE 17408
#define MLS_OFF 133120         // fp32 [8][256] (m,l state)
#define FLASH_SMEM 141312

#define SQRT_LOG2E 1.2011224087864498f

// Scratch (static device globals; no allocation)
__device__ float d_M[BB][2 * CC][NN];                     // pooled variants 3,5 (fp32)
__device__ __align__(16) __nv_bfloat16 d_Mt[BB][NN][DD];  // token-major, scaled (incl sqrt(log2e)), bf16
__device__ __align__(16) __half d_GXT[BB][IN][NN];        // g_x as [b][i][n], fp16
__device__ float d_S[3][BB][CC];
__device__ float d_sqrtV[BB][3];
__device__ float d_part[BB * NSPL][NN][IN];               // partial O (unnormalized)
__device__ float2 d_ml[BB * NSPL][NN];                    // partial (m, l), m in log2 domain

// ---------------- helpers ----------------
__device__ __forceinline__ uint32_t smem_u32(const void* p) {
    uint32_t a;
    asm("{ .reg .u64 t; cvta.to.shared.u64 t, %1; cvt.u32.u64 %0, t; }" : "=r"(a) : "l"(p));
    return a;
}
__device__ __forceinline__ uint32_t sw128(uint32_t bo) { return bo ^ ((bo >> 3) & 0x70); }

__device__ __forceinline__ void cpa16(uint32_t dst, const void* src) {
    asm volatile("cp.async.cg.shared.global [%0], [%1], 16;" :: "r"(dst), "l"(src));
}
__device__ __forceinline__ void cp_commit() { asm volatile("cp.async.commit_group;"); }
__device__ __forceinline__ void cp_wait0() { asm volatile("cp.async.wait_group 0;"); }
__device__ __forceinline__ void cp_wait1() { asm volatile("cp.async.wait_group 1;"); }

__device__ __forceinline__ void ldsm4(uint32_t* r, uint32_t addr) {
    asm volatile("ldmatrix.sync.aligned.m8n8.x4.shared.b16 {%0,%1,%2,%3}, [%4];"
                 : "=r"(r[0]), "=r"(r[1]), "=r"(r[2]), "=r"(r[3]) : "r"(addr));
}
__device__ __forceinline__ void mma_bf16(float* c, const uint32_t* a, uint32_t b0, uint32_t b1) {
    asm volatile("mma.sync.aligned.m16n8k16.row.col.f32.bf16.bf16.f32 "
                 "{%0,%1,%2,%3},{%4,%5,%6,%7},{%8,%9},{%0,%1,%2,%3};"
                 : "+f"(c[0]), "+f"(c[1]), "+f"(c[2]), "+f"(c[3])
                 : "r"(a[0]), "r"(a[1]), "r"(a[2]), "r"(a[3]), "r"(b0), "r"(b1));
}
__device__ __forceinline__ void mma_f16(float* c, const uint32_t* a, uint32_t b0, uint32_t b1) {
    asm volatile("mma.sync.aligned.m16n8k16.row.col.f32.f16.f16.f32 "
                 "{%0,%1,%2,%3},{%4,%5,%6,%7},{%8,%9},{%0,%1,%2,%3};"
                 : "+f"(c[0]), "+f"(c[1]), "+f"(c[2]), "+f"(c[3])
                 : "r"(a[0]), "r"(a[1]), "r"(a[2]), "r"(a[3]), "r"(b0), "r"(b1));
}
__device__ __forceinline__ float qredmax(float v) {
    v = fmaxf(v, __shfl_xor_sync(0xffffffffu, v, 1));
    v = fmaxf(v, __shfl_xor_sync(0xffffffffu, v, 2));
    return v;
}
__device__ __forceinline__ float qredsum(float v) {
    v += __shfl_xor_sync(0xffffffffu, v, 1);
    v += __shfl_xor_sync(0xffffffffu, v, 2);
    return v;
}

// ---------------- kernel 1: MERGED pool + gx (R10-proven) ----------------
__global__ __launch_bounds__(256) void prep_kernel(const float* __restrict__ x,
                                                   const float* __restrict__ Wg) {
    __shared__ __align__(16) char smraw[49152];
    const int bid = blockIdx.x;
    const int t = threadIdx.x;

    if (bid < 512) {
        const int c = bid & 255, b = bid >> 8;
        const float* xp = x + ((size_t)(b * CC + c)) * NN;
        float (*xs)[64] = (float (*)[64])smraw;
        float (*h3)[64] = (float (*)[64])(smraw + 16384);
        float (*h5)[64] = (float (*)[64])(smraw + 32768);

        for (int p = t; p < NN; p += 256) xs[p >> 6][p & 63] = xp[p];
        __syncthreads();
        for (int p = t; p < NN; p += 256) {
            int h = p >> 6, w = p & 63;
            float c0 = xs[h][w];
            float l1 = (w > 0)  ? xs[h][w - 1] : 0.f;
            float r1 = (w < 63) ? xs[h][w + 1] : 0.f;
            float l2 = (w > 1)  ? xs[h][w - 2] : 0.f;
            float r2 = (w < 62) ? xs[h][w + 2] : 0.f;
            h3[h][w] = l1 + c0 + r1;
            h5[h][w] = l2 + l1 + c0 + r1 + r2;
        }
        __syncthreads();
        float s1 = 0.f, s3 = 0.f, s5 = 0.f;
        float* M3 = &d_M[b][c][0];
        float* M5 = &d_M[b][CC + c][0];
        for (int p = t; p < NN; p += 256) {
            int h = p >> 6, w = p & 63;
            float v0 = xs[h][w];
            float u1 = (h > 0)  ? h3[h - 1][w] : 0.f;
            float dn1 = (h < 63) ? h3[h + 1][w] : 0.f;
            float u2 = (h > 1)  ? h5[h - 2][w] : 0.f;
            float dn2 = (h < 62) ? h5[h + 2][w] : 0.f;
            float u1b = (h > 0)  ? h5[h - 1][w] : 0.f;
            float dn1b = (h < 63) ? h5[h + 1][w] : 0.f;
            float p3 = (u1 + h3[h][w] + dn1) * (1.f / 9.f);
            float p5 = (u2 + u1b + h5[h][w] + dn1b + dn2) * (1.f / 25.f);
            M3[p] = p3; M5[p] = p5;
            s1 += v0; s3 += p3; s5 += p5;
        }
        __syncthreads();
        float* r1 = (float*)smraw;
        float* r3 = (float*)(smraw + 16384);
        float* r5 = (float*)(smraw + 32768);
        r1[t] = s1; r3[t] = s3; r5[t] = s5;
        __syncthreads();
        for (int off = 128; off > 0; off >>= 1) {
            if (t < off) { r1[t] += r1[t + off]; r3[t] += r3[t + off]; r5[t] += r5[t + off]; }
            __syncthreads();
        }
        if (t == 0) {
            d_S[0][b][c] = r1[0];
            d_S[1][b][c] = r3[0];
            d_S[2][b][c] = r5[0];
        }
    } else {
        const int gid = bid - 512;
        const int b = gid >> 7;
        const int n0 = (gid & 127) * 32;
        float (*Wgs)[33] = (float (*)[33])smraw;
        float* xsb = (float*)(smraw + 33792);
        const uint32_t xsb_u = smem_u32(xsb);
        const int i = t & 31, ng = t >> 5;
        const float* xb = x + (size_t)b * CC * NN;

        {
            int r = t >> 3, q = t & 7;
            cpa16(xsb_u + (r * 32 + q * 4) * 4, &xb[(size_t)r * NN + n0 + q * 4]);
            cp_commit();
        }
        #pragma unroll
        for (int it = 0; it < 32; it++) {
            int e = it * 256 + t;
            int ii = e >> 8, cc = e & 255;
            Wgs[cc][ii] = Wg[ii * CC + cc];
        }

        float acc[4] = {0.f, 0.f, 0.f, 0.f};
        for (int c = 0; c < 8; c++) {
            if (c + 1 < 8) {
                int r = t >> 3, q = t & 7;
                cpa16(xsb_u + (((c + 1) % 3) * 1024 + r * 32 + q * 4) * 4,
                      &xb[(size_t)((c + 1) * 32 + r) * NN + n0 + q * 4]);
                cp_commit();
                cp_wait1();
            } else {
                cp_wait0();
            }
            __syncthreads();
            const float* xsc = &xsb[(c % 3) * 1024];
            const int cbase = c * 32;
            #pragma unroll
            for (int cc = 0; cc < 32; cc++) {
                float w = Wgs[cbase + cc][i];
                float4 xv = *(const float4*)&xsc[cc * 32 + ng * 4];
                acc[0] += w * xv.x; acc[1] += w * xv.y; acc[2] += w * xv.z; acc[3] += w * xv.w;
            }
        }
        __half hv[4];
        #pragma unroll
        for (int j = 0; j < 4; j++) hv[j] = __float2half(acc[j]);
        *(uint2*)&d_GXT[b][i][n0 + ng * 4] = *(uint2*)hv;
    }
}

// ---------------- kernel 2: tiny V computation ----------------
__global__ void vcalc_kernel(const float* __restrict__ W1, const float* __restrict__ W2) {
    __shared__ float m[BB][3];
    const int t = threadIdx.x;
    if (t < 6) {
        int k = t % 3, b = t / 3;
        float s = 0.f;
        for (int c = 0; c < CC; c++) { float v = d_S[k][b][c]; s += v * v; }
        m[b][k] = s * (1.f / ((float)NN * (float)NN));
    }
    __syncthreads();
    if (t < BB) {
        int b = t;
        float h[16];
        #pragma unroll
        for (int i = 0; i < 16; i++)
            h[i] = W1[i * 3 + 0] * m[b][0] + W1[i * 3 + 1] * m[b][1] + W1[i * 3 + 2] * m[b][2];
        float o[3];
        #pragma unroll
        for (int j = 0; j < 3; j++) {
            float s = 0.f;
            #pragma unroll
            for (int i = 0; i < 16; i++) s += W2[j * 16 + i] * h[i];
            o[j] = s;
        }
        float mx = fmaxf(o[0], fmaxf(o[1], o[2]));
        float e0 = expf(o[0] - mx), e1 = expf(o[1] - mx), e2 = expf(o[2] - mx);
        float inv = 1.f / (e0 + e1 + e2);
        d_sqrtV[b][0] = sqrtf(e0 * inv);
        d_sqrtV[b][1] = sqrtf(e1 * inv);
        d_sqrtV[b][2] = sqrtf(e2 * inv);
    }
}

// ---------------- kernel 2b: transpose + scale (incl sqrt(log2e)) + bf16 ----------------
__global__ void split_kernel(const float* __restrict__ x) {
    const int b = blockIdx.y;
    const int dtile = blockIdx.x % NCH;
    const int ntile = blockIdx.x / NCH;
    const int d0 = dtile * 64, n0 = ntile * 64;
    const float s = d_sqrtV[b][dtile >> 2] * SQRT_LOG2E;
    const float* src = (dtile < 4) ? (x + ((size_t)b * CC + d0) * NN)
                                   : &d_M[b][d0 - CC][0];
    __shared__ float sme[64][65];
    const int t = threadIdx.x;
    #pragma unroll
    for (int it = 0; it < 4; it++) {
        int e = it * 256 + t;
        int r = e >> 4, c4 = (e & 15) << 2;
        float4 v = *(const float4*)&src[(size_t)r * NN + n0 + c4];
        sme[r][c4] = v.x; sme[r][c4 + 1] = v.y; sme[r][c4 + 2] = v.z; sme[r][c4 + 3] = v.w;
    }
    __syncthreads();
    #pragma unroll
    for (int it = 0; it < 2; it++) {
        int e = it * 256 + t;
        int r2 = e >> 3, g = e & 7;
        __nv_bfloat16 hv[8];
        #pragma unroll
        for (int q = 0; q < 8; q++)
            hv[q] = __float2bfloat16(sme[g * 8 + q][r2] * s);
        *(uint4*)&d_Mt[b][n0 + r2][d0 + g * 8] = *(uint4*)hv;
    }
}

// ---------------- kernel 4: split-K flash, ml-in-smem + pipelined B-fragments ----------------
// grid (32, SPLITS, BB), 256 threads (8 warps).
// warp: wr=warp>>1 rows wr*32..+31; wc=warp&1 cols wc*128..+127 (own (m,l,O) partial).
__global__ __launch_bounds__(256, 1) void flash11_kernel() {
    extern __shared__ __align__(16) char sm[];
    float* smf = (float*)sm;
    const uint32_t sb = smem_u32(sm);
    const int tid = threadIdx.x, warp = tid >> 5, lane = tid & 31;
    const int i0 = blockIdx.x * TMQ;
    const int split = blockIdx.y;
    const int b = blockIdx.z;
    const int wr = warp >> 1, wc = warp & 1;

    const int nl = (lane & 7) | ((lane & 16) >> 1);
    const int kh = (lane >> 3) & 1;

    // (m,l) state lives in smem: mls[idx][tid], idx: 0..3 = m[rt][ab], 4..7 = l[rt][ab]
    float* mls = smf + MLS_OFF / 4;
    #pragma unroll
    for (int idx = 0; idx < 4; idx++) mls[idx * 256 + tid] = -3.0e38f;
    #pragma unroll
    for (int idx = 4; idx < 8; idx++) mls[idx * 256 + tid] = 0.f;

    float yacc[2][4][4];
    #pragma unroll
    for (int rt = 0; rt < 2; rt++)
        #pragma unroll
        for (int ng = 0; ng < 4; ng++)
            #pragma unroll
            for (int q = 0; q < 4; q++) yacc[rt][ng][q] = 0.f;

    const __nv_bfloat16* Mb = &d_Mt[b][0][0];

    // prologue for tile jt: chunk 0 into stage 0 + VT into buffer jt&1
    auto prologue = [&](int jt) {
        const int j0 = split * KEYS + jt * TNK;
        #pragma unroll
        for (int it = 0; it < 4; it++) {
            int e = it * 256 + tid, r = e >> 3, g = e & 7;
            cpa16(sb + sw128(r * 128 + g * 16), Mb + (size_t)(i0 + r) * DD + g * 8);
        }
        #pragma unroll
        for (int it = 0; it < 8; it++) {
            int e = it * 256 + tid, r = e >> 3, g = e & 7;
            cpa16(sb + KOFF + sw128(r * 128 + g * 16), Mb + (size_t)(j0 + r) * DD + g * 8);
        }
        const uint32_t vb = sb + VTS_OFF + (jt & 1) * VT_STAGE;
        #pragma unroll
        for (int it = 0; it < 4; it++) {
            int e = it * 256 + tid, r = e >> 5, g = e & 31;
            cpa16(vb + r * VT_PITCH + g * 16, &d_GXT[b][r][j0 + g * 8]);
        }
        cp_commit();
    };
    prologue(0);

    for (int jt = 0; jt < NJT; jt++) {
        const int j0 = split * KEYS + jt * TNK;

        float acc[2][16][4];
        #pragma unroll
        for (int rt = 0; rt < 2; rt++)
            #pragma unroll
            for (int t = 0; t < 16; t++)
                #pragma unroll
                for (int q = 0; q < 4; q++) acc[rt][t][q] = 0.f;

        for (int c = 0; c < NCH; c++) {
            cp_wait0();
            __syncthreads();
            if (c + 1 < NCH) {
                uint32_t qb = sb + ((c + 1) & 1) * STAGE_BYTES;
                const int d0 = (c + 1) * KC;
                #pragma unroll
                for (int it = 0; it < 4; it++) {
                    int e = it * 256 + tid, r = e >> 3, g = e & 7;
                    cpa16(qb + sw128(r * 128 + g * 16), Mb + (size_t)(i0 + r) * DD + d0 + g * 8);
                }
                #pragma unroll
                for (int it = 0; it < 8; it++) {
                    int e = it * 256 + tid, r = e >> 3, g = e & 7;
                    cpa16(qb + KOFF + sw128(r * 128 + g * 16), Mb + (size_t)(j0 + r) * DD + d0 + g * 8);
                }
                cp_commit();
            }
            const uint32_t qb = sb + (c & 1) * STAGE_BYTES;
            const uint32_t kb = qb + KOFF;
            #pragma unroll
            for (int k16 = 0; k16 < 4; k16++) {
                uint32_t afr[2][4];
                ldsm4(afr[0], qb + sw128((wr * 32 + (lane & 15)) * 128 + k16 * 32 + (lane >> 4) * 16));
                ldsm4(afr[1], qb + sw128((wr * 32 + 16 + (lane & 15)) * 128 + k16 * 32 + (lane >> 4) * 16));
                // software-pipelined B fragments: ldsm for nt+1 issued before mmas of nt
                uint32_t bfr[2][4];
                ldsm4(bfr[0], kb + sw128((wc * 128 + nl) * 128 + k16 * 32 + kh * 16));
                #pragma unroll
                for (int nt = 0; nt < 8; nt++) {
                    if (nt < 7)
                        ldsm4(bfr[(nt + 1) & 1],
                              kb + sw128((wc * 128 + (nt + 1) * 16 + nl) * 128 + k16 * 32 + kh * 16));
                    const uint32_t* bp = bfr[nt & 1];
                    mma_bf16(acc[0][2 * nt],     afr[0], bp[0], bp[1]);
                    mma_bf16(acc[0][2 * nt + 1], afr[0], bp[2], bp[3]);
                    mma_bf16(acc[1][2 * nt],     afr[1], bp[0], bp[1]);
                    mma_bf16(acc[1][2 * nt + 1], afr[1], bp[2], bp[3]);
                }
            }
        }

        // hoist next tile's chunk-0 + VT loads over the serial phase
        if (jt + 1 < NJT) prologue(jt + 1);

        // ---- warp-local online softmax (barrier-free, log2 domain, ml in smem) ----
        float mna[2], mnb[2], lka[2], lkb[2];
        #pragma unroll
        for (int rt = 0; rt < 2; rt++) {
            float ma = -3.0e38f, mb2 = -3.0e38f;
            #pragma unroll
            for (int t = 0; t < 16; t++) {
                ma  = fmaxf(ma,  fmaxf(acc[rt][t][0], acc[rt][t][1]));
                mb2 = fmaxf(mb2, fmaxf(acc[rt][t][2], acc[rt][t][3]));
            }
            ma = qredmax(ma); mb2 = qredmax(mb2);
            float moa = mls[(rt * 2 + 0) * 256 + tid];
            float mob = mls[(rt * 2 + 1) * 256 + tid];
            float na = fmaxf(moa, ma), nb = fmaxf(mob, mb2);
            float sca = exp2f(moa - na), scb = exp2f(mob - nb);
            mls[(rt * 2 + 0) * 256 + tid] = na;
            mls[(rt * 2 + 1) * 256 + tid] = nb;
            lka[rt] = mls[(4 + rt * 2 + 0) * 256 + tid] * sca;
            lkb[rt] = mls[(4 + rt * 2 + 1) * 256 + tid] * scb;
            mna[rt] = na; mnb[rt] = nb;
            #pragma unroll
            for (int ng = 0; ng < 4; ng++) {
                yacc[rt][ng][0] *= sca; yacc[rt][ng][1] *= sca;
                yacc[rt][ng][2] *= scb; yacc[rt][ng][3] *= scb;
            }
        }

        // ---- fused exp2 + PV (P in registers; VT double-buffered) ----
        const uint32_t vtb = sb + VTS_OFF + (jt & 1) * VT_STAGE;
        float sa[2] = {0.f, 0.f}, sb2[2] = {0.f, 0.f};
        #pragma unroll
        for (int t = 0; t < 8; t++) {
            uint32_t bfr0[4], bfr1[4];
            ldsm4(bfr0, vtb + nl * VT_PITCH        + wc * 256 + t * 32 + kh * 16);
            ldsm4(bfr1, vtb + (16 + nl) * VT_PITCH + wc * 256 + t * 32 + kh * 16);
            #pragma unroll
            for (int rt = 0; rt < 2; rt++) {
                float e0 = exp2f(acc[rt][2 * t][0] - mna[rt]);
                float e1 = exp2f(acc[rt][2 * t][1] - mna[rt]);
                float e2 = exp2f(acc[rt][2 * t][2] - mnb[rt]);
                float e3 = exp2f(acc[rt][2 * t][3] - mnb[rt]);
                float e4 = exp2f(acc[rt][2 * t + 1][0] - mna[rt]);
                float e5 = exp2f(acc[rt][2 * t + 1][1] - mna[rt]);
                float e6 = exp2f(acc[rt][2 * t + 1][2] - mnb[rt]);
                float e7 = exp2f(acc[rt][2 * t + 1][3] - mnb[rt]);
                sa[rt]  += e0 + e1 + e4 + e5;
                sb2[rt] += e2 + e3 + e6 + e7;
                uint32_t a[4];
                __half2 h;
                h = __floats2half2_rn(e0, e1); a[0] = *(uint32_t*)&h;
                h = __floats2half2_rn(e2, e3); a[1] = *(uint32_t*)&h;
                h = __floats2half2_rn(e4, e5); a[2] = *(uint32_t*)&h;
                h = __floats2half2_rn(e6, e7); a[3] = *(uint32_t*)&h;
                mma_f16(yacc[rt][0], a, bfr0[0], bfr0[1]);
                mma_f16(yacc[rt][1], a, bfr0[2], bfr0[3]);
                mma_f16(yacc[rt][2], a, bfr1[0], bfr1[1]);
                mma_f16(yacc[rt][3], a, bfr1[2], bfr1[3]);
            }
        }
        #pragma unroll
        for (int rt = 0; rt < 2; rt++) {
            mls[(4 + rt * 2 + 0) * 256 + tid] = lka[rt] + qredsum(sa[rt]);
            mls[(4 + rt * 2 + 1) * 256 + tid] = lkb[rt] + qredsum(sb2[rt]);
        }
    }

    // ---- epilogue: straight register->global partial store (no barriers) ----
    const int sidx = (b * SPLITS + split) * 2 + wc;
    #pragma unroll
    for (int rt = 0; rt < 2; rt++) {
        int rowa = i0 + wr * 32 + rt * 16 + (lane >> 2);
        #pragma unroll
        for (int ng = 0; ng < 4; ng++) {
            int col = ng * 8 + (lane & 3) * 2;
            *(float2*)&d_part[sidx][rowa][col]     = make_float2(yacc[rt][ng][0], yacc[rt][ng][1]);
            *(float2*)&d_part[sidx][rowa + 8][col] = make_float2(yacc[rt][ng][2], yacc[rt][ng][3]);
        }
        if ((lane & 3) == 0) {
            d_ml[sidx][rowa]     = make_float2(mls[(rt * 2 + 0) * 256 + tid],
                                               mls[(4 + rt * 2 + 0) * 256 + tid]);
            d_ml[sidx][rowa + 8] = make_float2(mls[(rt * 2 + 1) * 256 + tid],
                                               mls[(4 + rt * 2 + 1) * 256 + tid]);
        }
    }
}

// ---------------- kernel 5: 4-way partial combine + Ww conv + residual ----------------
__global__ void combine_kernel(const float* __restrict__ x,
                               const float* __restrict__ Ww,
                               float* __restrict__ out) {
    const int b = blockIdx.y;
    const int r0 = blockIdx.x * 64;
    __shared__ float ysT[32][68];
    __shared__ float Ws[CC * IN];
    __shared__ float wS[NSPL][64];
    const int t = threadIdx.x;
    if (t < 64) {
        float2 ml[NSPL];
        float m = -3.0e38f;
        #pragma unroll
        for (int s = 0; s < NSPL; s++) {
            ml[s] = d_ml[b * NSPL + s][r0 + t];
            m = fmaxf(m, ml[s].x);
        }
        float lsum = 0.f, w[NSPL];
        #pragma unroll
        for (int s = 0; s < NSPL; s++) {
            w[s] = exp2f(ml[s].x - m);   // m's are in log2 domain
            lsum += ml[s].y * w[s];
        }
        float inv = 1.f / lsum;
        #pragma unroll
        for (int s = 0; s < NSPL; s++) wS[s][t] = w[s] * inv;
    }
    #pragma unroll
    for (int it = 0; it < 32; it++) Ws[it * 256 + t] = Ww[it * 256 + t];
    __syncthreads();
    for (int idx = t; idx < 64 * IN; idx += 256) {
        int rl = idx >> 5, col = idx & 31;
        float acc = 0.f;
        #pragma unroll
        for (int s = 0; s < NSPL; s++)
            acc += d_part[b * NSPL + s][r0 + rl][col] * wS[s][rl];
        ysT[col][rl] = acc;
    }
    __syncthreads();

    const int r = t & 63;
    const int cg = t >> 6;
    float yreg[IN];
    #pragma unroll
    for (int i = 0; i < IN; i++) yreg[i] = ysT[i][r];
    const float* xb = x + (size_t)b * CC * NN;
    float* ob = out + (size_t)b * CC * NN;
    #pragma unroll 4
    for (int k = 0; k < 64; k++) {
        int c = cg * 64 + k;
        float s = 0.f;
        #pragma unroll
        for (int q = 0; q < 8; q++) {
            float4 w4 = *(const float4*)&Ws[c * 32 + q * 4];
            s += w4.x * yreg[q * 4] + w4.y * yreg[q * 4 + 1] + w4.z * yreg[q * 4 + 2] + w4.w * yreg[q * 4 + 3];
        }
        ob[(size_t)c * NN + r0 + r] = s + xb[(size_t)c * NN + r0 + r];
    }
}

extern "C" void kernel_launch(void* const* d_in, const int* in_sizes, int n_in,
                              void* d_out, int out_size) {
    const float* x  = (const float*)d_in[0];
    const float* Wg = (const float*)d_in[1];
    const float* Ww = (const float*)d_in[2];
    const float* W1 = (const float*)d_in[3];
    const float* W2 = (const float*)d_in[4];
    float* out = (float*)d_out;

    static int configured = 0;
    if (!configured) {
        cudaFuncSetAttribute(flash11_kernel, cudaFuncAttributeMaxDynamicSharedMemorySize, FLASH_SMEM);
        configured = 1;
    }

    prep_kernel<<<768, 256>>>(x, Wg);
    vcalc_kernel<<<1, 64>>>(W1, W2);
    split_kernel<<<dim3(NCH * (NN / 64), BB), 256>>>(x);
    flash11_kernel<<<dim3(NN / TMQ, SPLITS, BB), 256, FLASH_SMEM>>>();
    combine_kernel<<<dim3(NN / 64, BB), 256>>>(x, Ww, out);
}